// round 2
// baseline (speedup 1.0000x reference)
#include <cuda_runtime.h>
#include <cstdint>

// Shapes (fixed by the problem)
#define BB 16
#define NN 128
#define DD 128

// Scratch (device globals — no allocations allowed)
// xcat  : [B*N, 384] = [hhat | deg*h | ehat]
// xcat2 : [B*N, 256] = [h | m]
// deg   : [B*N]
__device__ float g_xcat[BB * NN * 384];
__device__ float g_xcat2[BB * NN * 256];
__device__ float g_deg[BB * NN];

// ---------------------------------------------------------------------------
// Kernel A: per (b, j) block, 128 threads (thread = d).
//   ehat[b,j,d] = sum_i adj[b,i,j] * e[b,i,j,d]
//   hhat[b,j,d] = sum_i adj[b,i,j] * h[b,i,d]
//   deg [b,j]   = sum_i adj[b,i,j]
// Writes xcat = [hhat | deg*h | ehat], xcat2[:,0:128] = h, g_deg.
// Compacts nonzero adj rows so the e-load loop is unconditional (keeps MLP).
// ---------------------------------------------------------------------------
__global__ void __launch_bounds__(128) reduce_kernel(
    const float* __restrict__ h,
    const float* __restrict__ adj,
    const float* __restrict__ e,
    float* __restrict__ xcat,
    float* __restrict__ xcat2,
    float* __restrict__ deg_out)
{
    const int j = blockIdx.x;
    const int b = blockIdx.y;
    const int d = threadIdx.x;

    __shared__ float s_adj[NN];
    __shared__ float s_val[NN];
    __shared__ int   s_idx[NN];
    __shared__ int   s_cnt;
    __shared__ float s_deg;

    // adj column j for batch b: adj[b, i, j]
    s_adj[d] = adj[((size_t)b * NN + d) * NN + j];
    __syncthreads();

    if (d == 0) {
        int c = 0;
        float dg = 0.f;
        #pragma unroll 4
        for (int i = 0; i < NN; ++i) {
            float a = s_adj[i];
            dg += a;
            if (a != 0.f) { s_idx[c] = i; s_val[c] = a; ++c; }
        }
        s_cnt = c;
        s_deg = dg;
    }
    __syncthreads();

    const int cnt = s_cnt;
    const float deg = s_deg;

    // e[b,i,j,d] = e[ ((b*NN + i)*NN + j)*DD + d ]
    //   base (i=0): (b*NN*NN + j)*DD + d       stride over i: NN*DD
    const float* __restrict__ eb = e + ((size_t)b * NN * NN + (size_t)j) * DD + d;
    const float* __restrict__ hb = h + (size_t)b * NN * DD + d;

    float acc_e = 0.f, acc_h = 0.f;
    #pragma unroll 4
    for (int t = 0; t < cnt; ++t) {
        const float a = s_val[t];
        const int   i = s_idx[t];
        acc_e += a * eb[(size_t)i * (NN * DD)];  // e[b,i,j,d]
        acc_h += a * hb[(size_t)i * DD];         // h[b,i,d], L2-resident
    }

    const float hv = h[((size_t)b * NN + j) * DD + d];
    const size_t r = (size_t)b * NN + j;

    xcat[r * 384 + d]       = acc_h;        // hhat
    xcat[r * 384 + 128 + d] = deg * hv;     // deg * h
    xcat[r * 384 + 256 + d] = acc_e;        // ehat
    xcat2[r * 256 + d]      = hv;           // h (first half of concat)
    if (d == 0) deg_out[r] = deg;
}

// ---------------------------------------------------------------------------
// Tiled fp32 GEMM: C[row*ldc + coff + col] = sum_c A[row,c]*W[col,c]
//                                          + (rowscale?rowscale[row]:1)*bias[col]
// A: MxK row-major.  W: NxK row-major.  M=2048, N=128, K in {384,256}.
// BM=64, BN=32, BK=16, TM=4, TN=2, 256 threads, grid (N/32, M/64) = (4,32).
// ---------------------------------------------------------------------------
#define BM 64
#define BN 32
#define BK 16
#define TM 4
#define TN 2

__global__ void __launch_bounds__(256) gemm_bias_kernel(
    const float* __restrict__ A, int K,
    const float* __restrict__ W,
    const float* __restrict__ bias,
    const float* __restrict__ rowscale,   // may be nullptr
    float* __restrict__ C, int ldc, int coff)
{
    __shared__ float As[BK][BM + 1];
    __shared__ float Bs[BK][BN + 1];

    const int m0 = blockIdx.y * BM;
    const int n0 = blockIdx.x * BN;
    const int tid = threadIdx.x;
    const int tx = tid % (BN / TN);  // 0..15 (n groups)
    const int ty = tid / (BN / TN);  // 0..15 (m groups)

    // A tile load: 64x16 = 1024 floats, float4 per thread
    const int ar = tid >> 2;          // 0..63
    const int ac = (tid & 3) * 4;     // 0,4,8,12
    // W tile load: 32x16 = 512 floats, float2 per thread
    const int wr = tid >> 3;          // 0..31
    const int wc = (tid & 7) * 2;     // 0..14

    float acc[TM][TN];
    #pragma unroll
    for (int q = 0; q < TM; ++q)
        #pragma unroll
        for (int p = 0; p < TN; ++p) acc[q][p] = 0.f;

    for (int k0 = 0; k0 < K; k0 += BK) {
        float4 av = *(const float4*)(A + (size_t)(m0 + ar) * K + k0 + ac);
        As[ac + 0][ar] = av.x; As[ac + 1][ar] = av.y;
        As[ac + 2][ar] = av.z; As[ac + 3][ar] = av.w;
        float2 wv = *(const float2*)(W + (size_t)(n0 + wr) * K + k0 + wc);
        Bs[wc + 0][wr] = wv.x; Bs[wc + 1][wr] = wv.y;
        __syncthreads();

        #pragma unroll
        for (int kk = 0; kk < BK; ++kk) {
            float rm[TM], rn[TN];
            #pragma unroll
            for (int q = 0; q < TM; ++q) rm[q] = As[kk][ty * TM + q];
            #pragma unroll
            for (int p = 0; p < TN; ++p) rn[p] = Bs[kk][tx * TN + p];
            #pragma unroll
            for (int q = 0; q < TM; ++q)
                #pragma unroll
                for (int p = 0; p < TN; ++p) acc[q][p] += rm[q] * rn[p];
        }
        __syncthreads();
    }

    #pragma unroll
    for (int q = 0; q < TM; ++q) {
        const int row = m0 + ty * TM + q;
        const float rs = rowscale ? rowscale[row] : 1.f;
        #pragma unroll
        for (int p = 0; p < TN; ++p) {
            const int col = n0 + tx * TN + p;
            C[(size_t)row * ldc + coff + col] = acc[q][p] + rs * bias[col];
        }
    }
}

// ---------------------------------------------------------------------------
// kernel_launch: inputs in metadata order: h, adj, e, Wm, bm, Wu, bu
// output: (B, N, D) float32
// ---------------------------------------------------------------------------
extern "C" void kernel_launch(void* const* d_in, const int* in_sizes, int n_in,
                              void* d_out, int out_size)
{
    const float* h   = (const float*)d_in[0];
    const float* adj = (const float*)d_in[1];
    const float* e   = (const float*)d_in[2];
    const float* Wm  = (const float*)d_in[3];
    const float* bm  = (const float*)d_in[4];
    const float* Wu  = (const float*)d_in[5];
    const float* bu  = (const float*)d_in[6];
    float* out = (float*)d_out;

    float* xcat;  cudaGetSymbolAddress((void**)&xcat,  g_xcat);
    float* xcat2; cudaGetSymbolAddress((void**)&xcat2, g_xcat2);
    float* deg;   cudaGetSymbolAddress((void**)&deg,   g_deg);

    // A: fused adj-weighted reductions over i (the only HBM-heavy pass)
    {
        dim3 grid(NN, BB);
        reduce_kernel<<<grid, 128>>>(h, adj, e, xcat, xcat2, deg);
    }
    // B: m = xcat(2048x384) @ Wm^T(128x384) + deg*bm  -> xcat2[:,128:256]
    {
        dim3 grid(NN / BN, (BB * NN) / BM);
        gemm_bias_kernel<<<grid, 256>>>(xcat, 384, Wm, bm, deg, xcat2, 256, 128);
    }
    // C: out = xcat2(2048x256) @ Wu^T(128x256) + bu
    {
        dim3 grid(NN / BN, (BB * NN) / BM);
        gemm_bias_kernel<<<grid, 256>>>(xcat2, 256, Wu, bu, nullptr, out, 128, 0);
    }
}